// round 3
// baseline (speedup 1.0000x reference)
#include <cuda_runtime.h>
#include <math.h>

// Problem constants: preds [8,4,256,256] f32, targets [8,256,256] i32.
#define B 8
#define H 256
#define W 256
#define NCLS 3              // classes 1..3
#define NCB 24              // cb = (cls-1)*8 + b
#define IMG 65536           // H*W
#define NPIX 524288         // B*H*W
#define RWIN 8              // window radius; certified exact when min <= RWIN^2
#define NBLK 256            // fused-kernel block count

// -------- scratch (__device__ globals; no runtime allocation) --------
__device__ unsigned char d_gP[NCB * IMG];  // saturated squared 1-D row dist to pos
__device__ unsigned char d_gN[NCB * IMG];  // saturated squared 1-D row dist to neg
__device__ unsigned d_mask[NCLS * B * H * 8];  // row bitmasks (for exact fallback)
__device__ int   d_flag[NCB * W];       // per (cb, x): windowed min not certified
__device__ float d_partial[3 * NBLK];   // fused-kernel per-block sums per class
__device__ int   d_cnt[3 * NBLK];       // fused-kernel per-block pos counts

// ---------------------------------------------------------------------
// rowdist: reproduces the reference 1-D scan exactly.
//   f[x] = x - x'   (x' = nearest set bit <= x), else 512 + x + 1
//   r[x] = x'' - x  (x'' = nearest set bit >= x), else 512 + (256 - x)
// ---------------------------------------------------------------------
__device__ __forceinline__ int rowdist(const unsigned* m, int x, bool inv) {
    int w = x >> 5, b = x & 31;
    unsigned mw = inv ? ~m[w] : m[w];
    unsigned u = mw & (0xFFFFFFFFu >> (31 - b));
    int dl;
    if (u) {
        dl = b - (31 - __clz(u));
    } else {
        dl = 512 + x + 1;
        for (int i = w - 1; i >= 0; --i) {
            unsigned vi = inv ? ~m[i] : m[i];
            if (vi) { dl = x - (i * 32 + 31 - __clz(vi)); break; }
        }
    }
    unsigned u2 = mw & (0xFFFFFFFFu << b);
    int dr;
    if (u2) {
        dr = (__ffs(u2) - 1) - b;
    } else {
        dr = 512 + 256 - x;
        for (int i = w + 1; i < 8; ++i) {
            unsigned vi = inv ? ~m[i] : m[i];
            if (vi) { dr = i * 32 + (__ffs(vi) - 1) - x; break; }
        }
    }
    return dl < dr ? dl : dr;
}

// windowed column min (radius 8); used identically by fused kernel and fallback
__device__ __forceinline__ float winmin8(const float* v, int o) {
    float m = v[o + RWIN];
#pragma unroll
    for (int dy = 1; dy <= RWIN; ++dy) {
        float a = (float)(dy * dy);
        m = fminf(m, v[o + RWIN - dy] + a);
        m = fminf(m, v[o + RWIN + dy] + a);
    }
    return m;
}

// ---------------------------------------------------------------------
// K1: row pass. Computes saturated uint8 d^2 for pos/neg, 3 classes,
// and stores the row bitmasks for the exact fallback.
// ---------------------------------------------------------------------
__global__ __launch_bounds__(256) void k1_rows(const int* __restrict__ tg) {
    int row = blockIdx.x;              // b*256 + y
    int x = threadIdx.x;
    if (row < NCB) d_flag[row * W + x] = 0;
    int tv = tg[row * W + x];
    __shared__ unsigned m[8];
    int lane = x & 31, wi = x >> 5;
    for (int cls = 1; cls <= NCLS; ++cls) {
        unsigned bal = __ballot_sync(0xFFFFFFFFu, tv == cls);
        if (lane == 0) {
            m[wi] = bal;
            d_mask[((cls - 1) * (B * H) + row) * 8 + wi] = bal;
        }
        __syncthreads();
        unsigned mp[8];
#pragma unroll
        for (int i = 0; i < 8; ++i) mp[i] = m[i];
        __syncthreads();
        int dp = rowdist(mp, x, false);
        int dn = rowdist(mp, x, true);
        int off = (cls - 1) * 8 * IMG + row * 256 + x;
        int dp2 = dp * dp; if (dp2 > 255) dp2 = 255;
        int dn2 = dn * dn; if (dn2 > 255) dn2 = 255;
        d_gP[off] = (unsigned char)dp2;
        d_gN[off] = (unsigned char)dn2;
    }
}

// ---------------------------------------------------------------------
// K23 (fused): windowed column EDT + dmap + softmax + block reduction.
// Block = (b, 16-row tile, x-half), 128 threads (thread = x).
// dmap never materialized. Exact whenever windowed min <= 64 (outside
// candidates >= 81; uint8 saturation only affects values > 64 too).
// Uncertified columns are flagged for the exact fallback in k4.
// ---------------------------------------------------------------------
__global__ __launch_bounds__(128) void k23_fused(const float* __restrict__ preds) {
    int tid = threadIdx.x;
    int xh = blockIdx.x & 1;
    int ytile = (blockIdx.x >> 1) & 15;
    int b = blockIdx.x >> 5;
    int x = (xh << 7) + tid;
    int y0 = ytile << 4;

    float dmap[3][16];
    int cnt[3];

#pragma unroll
    for (int cls = 0; cls < 3; ++cls) {
        int cb = cls * 8 + b;
        const unsigned char* __restrict__ gp = d_gP + cb * IMG + x;
        const unsigned char* __restrict__ gn = d_gN + cb * IMG + x;
        float v[2 * RWIN + 16];
        bool bad = false;
#pragma unroll
        for (int r = 0; r < 2 * RWIN + 16; ++r) {
            int gy = y0 - RWIN + r;
            v[r] = (gy >= 0 && gy < H) ? (float)gp[gy << 8] : 1e30f;
        }
        float mp[16]; unsigned pb = 0;
#pragma unroll
        for (int o = 0; o < 16; ++o) {
            if (v[o + RWIN] == 0.0f) pb |= (1u << o);
            float m = winmin8(v, o);
            mp[o] = m;
            bad |= (m > 64.0f);
        }
#pragma unroll
        for (int r = 0; r < 2 * RWIN + 16; ++r) {
            int gy = y0 - RWIN + r;
            v[r] = (gy >= 0 && gy < H) ? (float)gn[gy << 8] : 1e30f;
        }
#pragma unroll
        for (int o = 0; o < 16; ++o) {
            float mn = winmin8(v, o);
            bad |= (mn > 64.0f);
            dmap[cls][o] = ((pb >> o) & 1u) ? (1.0f - sqrtf(mn)) : sqrtf(mp[o]);
        }
        if (bad) d_flag[cb * W + x] = 1;    // races benign (all write 1)
        cnt[cls] = __popc(pb);
    }

    // softmax + dot with dmap
    float s0 = 0.0f, s1 = 0.0f, s2 = 0.0f;
    const float* pbase = preds + b * (4 * IMG) + (y0 << 8) + x;
#pragma unroll
    for (int o = 0; o < 16; ++o) {
        const float* p = pbase + (o << 8);
        float e0 = __expf(p[0]);
        float e1 = __expf(p[IMG]);
        float e2 = __expf(p[2 * IMG]);
        float e3 = __expf(p[3 * IMG]);
        float inv = 1.0f / (e0 + e1 + e2 + e3);
        s0 += dmap[0][o] * (e1 * inv);
        s1 += dmap[1][o] * (e2 * inv);
        s2 += dmap[2][o] * (e3 * inv);
    }

    // block reduction: 4 warps
    int c0 = cnt[0], c1 = cnt[1], c2 = cnt[2];
#pragma unroll
    for (int off = 16; off; off >>= 1) {
        s0 += __shfl_down_sync(0xFFFFFFFFu, s0, off);
        s1 += __shfl_down_sync(0xFFFFFFFFu, s1, off);
        s2 += __shfl_down_sync(0xFFFFFFFFu, s2, off);
        c0 += __shfl_down_sync(0xFFFFFFFFu, c0, off);
        c1 += __shfl_down_sync(0xFFFFFFFFu, c1, off);
        c2 += __shfl_down_sync(0xFFFFFFFFu, c2, off);
    }
    __shared__ float sm[4][3];
    __shared__ int smc[4][3];
    int w = tid >> 5;
    if ((tid & 31) == 0) {
        sm[w][0] = s0; sm[w][1] = s1; sm[w][2] = s2;
        smc[w][0] = c0; smc[w][1] = c1; smc[w][2] = c2;
    }
    __syncthreads();
    if (tid < 3) {
        float t = sm[0][tid] + sm[1][tid] + sm[2][tid] + sm[3][tid];
        int ci = smc[0][tid] + smc[1][tid] + smc[2][tid] + smc[3][tid];
        d_partial[tid * NBLK + blockIdx.x] = t;
        d_cnt[tid * NBLK + blockIdx.x] = ci;
    }
}

// ---------------------------------------------------------------------
// Exact fallback for one flagged column: exact g from masks, exact O(H^2)
// column min, replicate the approximate path bit-exactly, accumulate a
// deterministic correction. Only runs when a window wasn't certified —
// never on typical inputs.
// ---------------------------------------------------------------------
__device__ void fix_column(int cb, int x, const float* preds, float* adj) {
    int cls = cb >> 3;      // 0-based
    int b = cb & 7;
    float gpe[256], gne[256];
    for (int y = 0; y < 256; ++y) {
        unsigned mw[8];
#pragma unroll
        for (int i = 0; i < 8; ++i)
            mw[i] = d_mask[(cls * (B * H) + b * 256 + y) * 8 + i];
        int dp = rowdist(mw, x, false);
        int dn = rowdist(mw, x, true);
        gpe[y] = (float)(dp * dp);
        gne[y] = (float)(dn * dn);
    }
    const unsigned char* gp = d_gP + cb * IMG + x;
    const unsigned char* gn = d_gN + cb * IMG + x;
    float delta = 0.0f;
    for (int y = 0; y < 256; ++y) {
        float mpE = 1e30f, mnE = 1e30f;
        for (int yp = 0; yp < 256; ++yp) {
            float dy2 = (float)((y - yp) * (y - yp));
            mpE = fminf(mpE, gpe[yp] + dy2);
            mnE = fminf(mnE, gne[yp] + dy2);
        }
        bool pos = (gp[y << 8] == 0);
        float exact = pos ? (1.0f - sqrtf(mnE)) : sqrtf(mpE);
        // replicate approximate path
        int y0 = y & ~15, o = y & 15;
        float v[2 * RWIN + 16];
        for (int r = 0; r < 2 * RWIN + 16; ++r) {
            int gy = y0 - RWIN + r;
            v[r] = (gy >= 0 && gy < H) ? (float)gp[gy << 8] : 1e30f;
        }
        float mpA = winmin8(v, o);
        for (int r = 0; r < 2 * RWIN + 16; ++r) {
            int gy = y0 - RWIN + r;
            v[r] = (gy >= 0 && gy < H) ? (float)gn[gy << 8] : 1e30f;
        }
        float mnA = winmin8(v, o);
        float approx = pos ? (1.0f - sqrtf(mnA)) : sqrtf(mpA);
        if (exact != approx) {
            const float* p = preds + b * (4 * IMG) + (y << 8) + x;
            float e0 = __expf(p[0]);
            float e1 = __expf(p[IMG]);
            float e2 = __expf(p[2 * IMG]);
            float e3 = __expf(p[3 * IMG]);
            float inv = 1.0f / (e0 + e1 + e2 + e3);
            float pr = ((cls == 0) ? e1 : (cls == 1) ? e2 : e3) * inv;
            delta += (exact - approx) * pr;
        }
    }
    adj[cls] += delta;
}

// ---------------------------------------------------------------------
// K4: final deterministic reduction + fallback corrections + has/count.
// ---------------------------------------------------------------------
__global__ __launch_bounds__(256) void k4_final(const float* __restrict__ preds,
                                                float* __restrict__ out) {
    __shared__ float red[256];
    __shared__ float tot[3];
    __shared__ float ccnt[3];
    __shared__ int flagged;
    __shared__ float adj[3];
    int tid = threadIdx.x;
    for (int q = 0; q < 3; ++q) {
        red[tid] = d_partial[q * NBLK + tid];
        __syncthreads();
        for (int st = 128; st; st >>= 1) {
            if (tid < st) red[tid] += red[tid + st];
            __syncthreads();
        }
        if (tid == 0) tot[q] = red[0];
        __syncthreads();
    }
    for (int q = 0; q < 3; ++q) {
        red[tid] = (float)d_cnt[q * NBLK + tid];
        __syncthreads();
        for (int st = 128; st; st >>= 1) {
            if (tid < st) red[tid] += red[tid + st];
            __syncthreads();
        }
        if (tid == 0) ccnt[q] = red[0];
        __syncthreads();
    }
    if (tid == 0) { flagged = 0; adj[0] = adj[1] = adj[2] = 0.0f; }
    __syncthreads();
    int f = 0;
    for (int i = tid; i < NCB * W; i += 256) f |= d_flag[i];
    if (f) atomicOr(&flagged, 1);
    __syncthreads();
    if (flagged && tid == 0) {
        for (int cb = 0; cb < NCB; ++cb)
            for (int x = 0; x < W; ++x)
                if (d_flag[cb * W + x]) fix_column(cb, x, preds, adj);
    }
    __syncthreads();
    if (tid == 0) {
        float total = 0.0f, count = 0.0f;
        for (int c = 0; c < 3; ++c) {
            if (ccnt[c] > 0.0f) {
                total += (tot[c] + adj[c]) * (1.0f / (float)NPIX);
                count += 1.0f;
            }
        }
        out[0] = (count > 0.0f) ? (total / count) : 0.0f;
    }
}

extern "C" void kernel_launch(void* const* d_in, const int* in_sizes, int n_in,
                              void* d_out, int out_size) {
    const float* preds = (const float*)d_in[0];
    const int* targets = (const int*)d_in[1];
    float* out = (float*)d_out;

    k1_rows<<<B * H, 256>>>(targets);
    k23_fused<<<NBLK, 128>>>(preds);
    k4_final<<<1, 256>>>(preds, out);
}

// round 4
// speedup vs baseline: 1.4486x; 1.4486x over previous
#include <cuda_runtime.h>
#include <cuda_fp16.h>
#include <math.h>

// Problem constants: preds [8,4,256,256] f32, targets [8,256,256] i32.
#define B 8
#define H 256
#define W 256
#define NCLS 3              // classes 1..3
#define NCB 24              // cb = (cls-1)*8 + b
#define IMG 65536           // H*W
#define NPIX 524288         // B*H*W
#define RWIN 8              // window radius; certified exact when min <= 64
#define NBLK2 256           // fused-kernel block count

// -------- scratch (__device__ globals; no runtime allocation) --------
__device__ __half d_gP[NCB * IMG];   // squared 1-D row dist to pos: {0..64} or 255
__device__ __half d_gN[NCB * IMG];   // same for neg
__device__ unsigned d_mask[NCLS * B * H * 8];  // row bitmasks (exact fallback)
__device__ int   d_flag[NCB * 128];  // per (cb, xh-pair): window not certified
__device__ float d_partial[3 * NBLK2];
__device__ int   d_cnt[3 * NBLK2];

// ---------------------------------------------------------------------
// Windowed row distance^2: exact for d <= 8, else 255 (>= true clamp).
// win holds mask bits for positions x-8 .. x+16 (bit 8 = x).
// ---------------------------------------------------------------------
__device__ __forceinline__ int win_d2(unsigned win) {
    unsigned t = win & 0x1FFu;              // positions x-8..x
    int dl = t ? (8 - (31 - __clz(t))) : 16;
    unsigned t2 = (win >> 8) & 0x1FFu;      // positions x..x+8
    int dr = t2 ? (__ffs(t2) - 1) : 16;
    int d = dl < dr ? dl : dr;
    int d2 = d * d;
    return d2 > 255 ? 255 : d2;
}

// ---------------------------------------------------------------------
// K1: row pass, windowed. Stores half g for pos/neg, 3 classes, plus row
// bitmasks for the exact fallback.
// ---------------------------------------------------------------------
__global__ __launch_bounds__(256) void k1_rows(const int* __restrict__ tg) {
    int row = blockIdx.x;              // b*256 + y
    int x = threadIdx.x;
    if (row < NCB && x < 128) d_flag[row * 128 + x] = 0;
    int tv = tg[row * W + x];
    __shared__ unsigned m[8];
    int lane = x & 31, wi = x >> 5;
    int s = x - 8;
    int idx = s >> 5;                  // arithmetic shift: -1..7
    int off = s & 31;
#pragma unroll
    for (int cls = 1; cls <= NCLS; ++cls) {
        unsigned bal = __ballot_sync(0xFFFFFFFFu, tv == cls);
        if (lane == 0) {
            m[wi] = bal;
            d_mask[((cls - 1) * (B * H) + row) * 8 + wi] = bal;
        }
        __syncthreads();
        unsigned wloP = (idx >= 0) ? m[idx] : 0u;
        unsigned whiP = (idx + 1 < 8) ? m[idx + 1] : 0u;
        unsigned wloN = (idx >= 0) ? ~m[idx] : 0u;
        unsigned whiN = (idx + 1 < 8) ? ~m[idx + 1] : 0u;
        __syncthreads();
        unsigned winP = (unsigned)(((((unsigned long long)whiP) << 32) | wloP) >> off);
        unsigned winN = (unsigned)(((((unsigned long long)whiN) << 32) | wloN) >> off);
        int o0 = (cls - 1) * 8 * IMG + row * 256 + x;
        d_gP[o0] = __float2half_rn((float)win_d2(winP));
        d_gN[o0] = __float2half_rn((float)win_d2(winN));
    }
}

// windowed column min over half2 (2 x's per op); exact integer arithmetic
__device__ __forceinline__ __half2 wmin8h(const __half2* v, int o) {
    __half2 m = v[o + RWIN];
#pragma unroll
    for (int dy = 1; dy <= RWIN; ++dy) {
        __half2 dd = __float2half2_rn((float)(dy * dy));
        m = __hmin2(m, __hadd2(v[o + RWIN - dy], dd));
        m = __hmin2(m, __hadd2(v[o + RWIN + dy], dd));
    }
    return m;
}

// ---------------------------------------------------------------------
// K23 (fused): half2 windowed column EDT + dmap + softmax + reduction.
// Grid: 8 b * 32 ytiles(8 rows) = 256 blocks. 256 threads =
// (xh 0..127 half2-pair of x) x (ys 0..1), each thread 4 rows x 2 x's.
// Certified exact when windowed min <= 64 (else flag -> exact fallback).
// ---------------------------------------------------------------------
__global__ __launch_bounds__(256) void k23_fused(const float* __restrict__ preds) {
    int tid = threadIdx.x;
    int xh = tid & 127;
    int ys = tid >> 7;
    int b = blockIdx.x >> 5;
    int y0 = (blockIdx.x & 31) << 3;
    int yo0 = y0 + ys * 4;

    __half2 mP[3][4], mN[3][4], cz[3][4];
    const __half2 HINF = __float2half2_rn(1024.0f);

#pragma unroll
    for (int cls = 0; cls < 3; ++cls) {
        int cb = cls * 8 + b;
        const __half2* __restrict__ gp = ((const __half2*)d_gP) + cb * (IMG / 2) + xh;
        const __half2* __restrict__ gn = ((const __half2*)d_gN) + cb * (IMG / 2) + xh;
        __half2 v[2 * RWIN + 4];
#pragma unroll
        for (int r = 0; r < 2 * RWIN + 4; ++r) {
            int gy = yo0 - RWIN + r;
            v[r] = (gy >= 0 && gy < H) ? gp[gy * 128] : HINF;
        }
#pragma unroll
        for (int o = 0; o < 4; ++o) {
            cz[cls][o] = v[o + RWIN];
            mP[cls][o] = wmin8h(v, o);
        }
#pragma unroll
        for (int r = 0; r < 2 * RWIN + 4; ++r) {
            int gy = yo0 - RWIN + r;
            v[r] = (gy >= 0 && gy < H) ? gn[gy * 128] : HINF;
        }
#pragma unroll
        for (int o = 0; o < 4; ++o) mN[cls][o] = wmin8h(v, o);
    }

    float s[3] = {0.f, 0.f, 0.f};
    int cnt[3] = {0, 0, 0};
    bool bad[3] = {false, false, false};
    const float* pb = preds + b * (4 * IMG) + yo0 * 256 + xh * 2;
#pragma unroll
    for (int o = 0; o < 4; ++o) {
        const float* p = pb + (o << 8);
        float2 a0 = *(const float2*)(p);
        float2 a1 = *(const float2*)(p + IMG);
        float2 a2 = *(const float2*)(p + 2 * IMG);
        float2 a3 = *(const float2*)(p + 3 * IMG);
#pragma unroll
        for (int e = 0; e < 2; ++e) {
            float q0 = e ? a0.y : a0.x, q1 = e ? a1.y : a1.x;
            float q2 = e ? a2.y : a2.x, q3 = e ? a3.y : a3.x;
            float e0 = __expf(q0), e1 = __expf(q1), e2 = __expf(q2), e3 = __expf(q3);
            float inv = 1.0f / (e0 + e1 + e2 + e3);
            float pr[3] = {e1 * inv, e2 * inv, e3 * inv};
#pragma unroll
            for (int c = 0; c < 3; ++c) {
                float gcz = e ? __high2float(cz[c][o]) : __low2float(cz[c][o]);
                float mp = e ? __high2float(mP[c][o]) : __low2float(mP[c][o]);
                float mn = e ? __high2float(mN[c][o]) : __low2float(mN[c][o]);
                bad[c] |= (mp > 64.0f) || (mn > 64.0f);
                bool pos = (gcz == 0.0f);
                float dm = pos ? (1.0f - sqrtf(mn)) : sqrtf(mp);
                s[c] += dm * pr[c];
                cnt[c] += pos ? 1 : 0;
            }
        }
    }
#pragma unroll
    for (int c = 0; c < 3; ++c)
        if (bad[c]) d_flag[(c * 8 + b) * 128 + xh] = 1;   // races benign

    // block reduction
#pragma unroll
    for (int off = 16; off; off >>= 1) {
#pragma unroll
        for (int c = 0; c < 3; ++c) {
            s[c] += __shfl_down_sync(0xFFFFFFFFu, s[c], off);
            cnt[c] += __shfl_down_sync(0xFFFFFFFFu, cnt[c], off);
        }
    }
    __shared__ float sm[8][3];
    __shared__ int smc[8][3];
    int w = tid >> 5;
    if ((tid & 31) == 0) {
#pragma unroll
        for (int c = 0; c < 3; ++c) { sm[w][c] = s[c]; smc[w][c] = cnt[c]; }
    }
    __syncthreads();
    if (tid < 3) {
        float t = 0.0f; int ci = 0;
#pragma unroll
        for (int i = 0; i < 8; ++i) { t += sm[i][tid]; ci += smc[i][tid]; }
        d_partial[tid * NBLK2 + blockIdx.x] = t;
        d_cnt[tid * NBLK2 + blockIdx.x] = ci;
    }
}

// ---------------------------------------------------------------------
// Exact reference rowdist (full scans) — fallback only.
// ---------------------------------------------------------------------
__device__ int rowdist_full(const unsigned* m, int x, bool inv) {
    int w = x >> 5, b = x & 31;
    unsigned mw = inv ? ~m[w] : m[w];
    unsigned u = mw & (0xFFFFFFFFu >> (31 - b));
    int dl;
    if (u) {
        dl = b - (31 - __clz(u));
    } else {
        dl = 512 + x + 1;
        for (int i = w - 1; i >= 0; --i) {
            unsigned vi = inv ? ~m[i] : m[i];
            if (vi) { dl = x - (i * 32 + 31 - __clz(vi)); break; }
        }
    }
    unsigned u2 = mw & (0xFFFFFFFFu << b);
    int dr;
    if (u2) {
        dr = (__ffs(u2) - 1) - b;
    } else {
        dr = 512 + 256 - x;
        for (int i = w + 1; i < 8; ++i) {
            unsigned vi = inv ? ~m[i] : m[i];
            if (vi) { dr = i * 32 + (__ffs(vi) - 1) - x; break; }
        }
    }
    return dl < dr ? dl : dr;
}

// Exact fallback for one flagged column: exact EDT from masks, replicate
// the approximate (windowed, clamped) path bit-exactly, and accumulate a
// deterministic correction. Never executes on typical inputs.
__device__ void fix_column(int cb, int x, const float* preds, float* adj) {
    int cls = cb >> 3;      // 0-based
    int b = cb & 7;
    float gpe[256], gne[256];
    for (int y = 0; y < 256; ++y) {
        unsigned mw[8];
#pragma unroll
        for (int i = 0; i < 8; ++i)
            mw[i] = d_mask[(cls * (B * H) + b * 256 + y) * 8 + i];
        int dp = rowdist_full(mw, x, false);
        int dn = rowdist_full(mw, x, true);
        gpe[y] = (float)(dp * dp);
        gne[y] = (float)(dn * dn);
    }
    const __half* gp = d_gP + cb * IMG + x;
    const __half* gn = d_gN + cb * IMG + x;
    float delta = 0.0f;
    for (int y = 0; y < 256; ++y) {
        float mpE = 1e30f, mnE = 1e30f;
        for (int yp = 0; yp < 256; ++yp) {
            float dy2 = (float)((y - yp) * (y - yp));
            mpE = fminf(mpE, gpe[yp] + dy2);
            mnE = fminf(mnE, gne[yp] + dy2);
        }
        bool pos = (__half2float(gp[y << 8]) == 0.0f);
        float exact = pos ? (1.0f - sqrtf(mnE)) : sqrtf(mpE);
        // replicate approximate path (same values/ops as k23 in exact ints)
        float mpA = 1e30f, mnA = 1e30f;
        for (int dy = -RWIN; dy <= RWIN; ++dy) {
            int gy = y + dy;
            float Sp = (gy >= 0 && gy < H) ? __half2float(gp[gy << 8]) : 1024.0f;
            float Sn = (gy >= 0 && gy < H) ? __half2float(gn[gy << 8]) : 1024.0f;
            float d2 = (float)(dy * dy);
            mpA = fminf(mpA, Sp + d2);
            mnA = fminf(mnA, Sn + d2);
        }
        float approx = pos ? (1.0f - sqrtf(mnA)) : sqrtf(mpA);
        if (exact != approx) {
            const float* p = preds + b * (4 * IMG) + (y << 8) + x;
            float e0 = __expf(p[0]);
            float e1 = __expf(p[IMG]);
            float e2 = __expf(p[2 * IMG]);
            float e3 = __expf(p[3 * IMG]);
            float inv = 1.0f / (e0 + e1 + e2 + e3);
            float pr = ((cls == 0) ? e1 : (cls == 1) ? e2 : e3) * inv;
            delta += (exact - approx) * pr;
        }
    }
    adj[cls] += delta;
}

// ---------------------------------------------------------------------
// K4: final deterministic reduction + fallback corrections + has/count.
// ---------------------------------------------------------------------
__global__ __launch_bounds__(256) void k4_final(const float* __restrict__ preds,
                                                float* __restrict__ out) {
    __shared__ float red[256];
    __shared__ float tot[3];
    __shared__ float ccnt[3];
    __shared__ int flagged;
    __shared__ float adj[3];
    int tid = threadIdx.x;
    for (int q = 0; q < 3; ++q) {
        red[tid] = d_partial[q * NBLK2 + tid];
        __syncthreads();
        for (int st = 128; st; st >>= 1) {
            if (tid < st) red[tid] += red[tid + st];
            __syncthreads();
        }
        if (tid == 0) tot[q] = red[0];
        __syncthreads();
    }
    for (int q = 0; q < 3; ++q) {
        red[tid] = (float)d_cnt[q * NBLK2 + tid];
        __syncthreads();
        for (int st = 128; st; st >>= 1) {
            if (tid < st) red[tid] += red[tid + st];
            __syncthreads();
        }
        if (tid == 0) ccnt[q] = red[0];
        __syncthreads();
    }
    if (tid == 0) { flagged = 0; adj[0] = adj[1] = adj[2] = 0.0f; }
    __syncthreads();
    int f = 0;
    for (int i = tid; i < NCB * 128; i += 256) f |= d_flag[i];
    if (f) atomicOr(&flagged, 1);
    __syncthreads();
    if (flagged && tid == 0) {
        for (int cb = 0; cb < NCB; ++cb)
            for (int xh = 0; xh < 128; ++xh)
                if (d_flag[cb * 128 + xh]) {
                    fix_column(cb, 2 * xh, preds, adj);
                    fix_column(cb, 2 * xh + 1, preds, adj);
                }
    }
    __syncthreads();
    if (tid == 0) {
        float total = 0.0f, count = 0.0f;
        for (int c = 0; c < 3; ++c) {
            if (ccnt[c] > 0.0f) {
                total += (tot[c] + adj[c]) * (1.0f / (float)NPIX);
                count += 1.0f;
            }
        }
        out[0] = (count > 0.0f) ? (total / count) : 0.0f;
    }
}

extern "C" void kernel_launch(void* const* d_in, const int* in_sizes, int n_in,
                              void* d_out, int out_size) {
    const float* preds = (const float*)d_in[0];
    const int* targets = (const int*)d_in[1];
    float* out = (float*)d_out;

    k1_rows<<<B * H, 256>>>(targets);
    k23_fused<<<NBLK2, 256>>>(preds);
    k4_final<<<1, 256>>>(preds, out);
}